// round 13
// baseline (speedup 1.0000x reference)
#include <cuda_runtime.h>
#include <cuda_bf16.h>
#include <math.h>
#include <stdint.h>

#define BB   2
#define CC   128
#define HH   512
#define WW   512
#define NWIN 4096
#define NWF  1228
#define NPAIR (NWF/2)
#define HWSZ ((size_t)HH*(size_t)WW)
#define SCALEF 0.08838834764831845f

// strides (elements)
#define SA 136
#define SP 72
#define SD 132

// smem byte offsets
#define O_A   1024              // WFH 128x136 bf16
#define O_B   35840             // WFL
#define O_C   70656             // WTH
#define O_D   105472            // WTL
#define O_E   140288            // EB ; DUMP (fp32 128x132 = 67584B) overlays E..207872
#define O_F   175104            // KG (kg 64 rows / k2 128 rows, spills into VGT: dead then)
#define O_VGT (O_F+17408)
#define O_P   210944            // PB 128x72 bf16
#define SMEM_SZ 229376

// -------- device scratch --------
__device__ int   d_sel[BB * NWF];
__device__ unsigned d_selmask[BB * 128];
__device__ float d_g[BB * 64 * CC];
__device__ __nv_bfloat16 d_kgb[BB][64 * 128];
__device__ __nv_bfloat16 d_vgtb[BB][128 * 64];
// weight images (bf16): 0=qg 1=l0 2=q2 3=k2 4=v2 5=pw
__device__ __nv_bfloat16 d_whi[6][128 * 128];

// ---------------- helpers ----------------
__device__ __forceinline__ uint32_t pkf(float a, float b){
    __nv_bfloat162 t = __floats2bfloat162_rn(a, b);
    return *reinterpret_cast<uint32_t*>(&t);
}
__device__ __forceinline__ float2 up2(uint32_t u){
    __nv_bfloat162 b = *reinterpret_cast<__nv_bfloat162*>(&u);
    return make_float2(__bfloat162float(b.x), __bfloat162float(b.y));
}
__device__ __forceinline__ void split2(float x0, float x1, uint32_t& h, uint32_t& l){
    __nv_bfloat16 b0 = __float2bfloat16_rn(x0), b1 = __float2bfloat16_rn(x1);
    __nv_bfloat162 hb; hb.x = b0; hb.y = b1;
    h = *reinterpret_cast<uint32_t*>(&hb);
    l = pkf(x0 - __bfloat162float(b0), x1 - __bfloat162float(b1));
}
__device__ __forceinline__ float geluf(float x){
    return 0.5f * x * (1.f + erff(x * 0.70710678118654752f));
}
__device__ __forceinline__ void mma16816(float* d, const uint32_t* a, uint32_t b0, uint32_t b1){
    asm("mma.sync.aligned.m16n8k16.row.col.f32.bf16.bf16.f32 "
        "{%0,%1,%2,%3},{%4,%5,%6,%7},{%8,%9},{%0,%1,%2,%3};"
        : "+f"(d[0]), "+f"(d[1]), "+f"(d[2]), "+f"(d[3])
        : "r"(a[0]), "r"(a[1]), "r"(a[2]), "r"(a[3]), "r"(b0), "r"(b1));
}
__device__ __forceinline__ void ldsm4(uint32_t* r, uint32_t addr){
    asm volatile("ldmatrix.sync.aligned.m8n8.x4.shared.b16 {%0,%1,%2,%3}, [%4];"
        : "=r"(r[0]), "=r"(r[1]), "=r"(r[2]), "=r"(r[3]) : "r"(addr));
}

// Generic ldmatrix GEMM pass. A row-major [m][k] rows arow0..+MI*16-1,
// B row-major [n][k] rows bcol0..+NB*16-1, K = KS*16.
template<int MI, int NB, int KS>
__device__ __forceinline__ void gpassG(float (*acc)[4],
    const __nv_bfloat16* A, int sA, int arow0,
    const __nv_bfloat16* B, int sB, int bcol0, int lane)
{
    uint32_t aa[MI], bb[NB];
    uint32_t abase = (uint32_t)__cvta_generic_to_shared(
        A + (arow0 + (lane & 7) + (((lane >> 3) & 1) << 3)) * sA + ((lane >> 4) << 3));
    #pragma unroll
    for (int mi = 0; mi < MI; mi++) aa[mi] = abase + mi * 16 * sA * 2;
    uint32_t bbase = (uint32_t)__cvta_generic_to_shared(
        B + (bcol0 + (lane & 7) + ((lane >> 4) << 3)) * sB + (((lane >> 3) & 1) << 3));
    #pragma unroll
    for (int nb = 0; nb < NB; nb++) bb[nb] = bbase + nb * 16 * sB * 2;
    #pragma unroll
    for (int ks = 0; ks < KS; ks++) {
        uint32_t ar[MI][4];
        #pragma unroll
        for (int mi = 0; mi < MI; mi++) ldsm4(ar[mi], aa[mi] + ks * 32);
        #pragma unroll
        for (int nb = 0; nb < NB; nb++) {
            uint32_t rbv[4]; ldsm4(rbv, bb[nb] + ks * 32);
            #pragma unroll
            for (int mi = 0; mi < MI; mi++) {
                mma16816(acc[(mi * NB + nb) * 2],     ar[mi], rbv[0], rbv[1]);
                mma16816(acc[(mi * NB + nb) * 2 + 1], ar[mi], rbv[2], rbv[3]);
            }
        }
    }
}

#define ZACC(A, N) { _Pragma("unroll") for (int _i = 0; _i < (N); _i++) { (A)[_i][0]=0.f;(A)[_i][1]=0.f;(A)[_i][2]=0.f;(A)[_i][3]=0.f; } }

// ============ prep: sort+select (1024t) | weight conv | pool-only ============
__global__ void prep_kernel(const float* __restrict__ unc,
                            const float* __restrict__ qgw,
                            const float* __restrict__ l0w,
                            const float* __restrict__ qkvw,
                            const float* __restrict__ pw,
                            const float* __restrict__ fm) {
    __shared__ __align__(16) unsigned char sm[32768];
    int tid = threadIdx.x;               // 1024
    int bid = blockIdx.x;
    if (bid < BB) {                      // ---- sort/select ----
        unsigned long long* key = (unsigned long long*)sm;
        int b = bid;
        for (int i = tid; i < 128; i += 1024) d_selmask[b * 128 + i] = 0;
        for (int i = tid; i < NWIN; i += 1024) {
            int hy = i >> 6, wx = i & 63;
            const float* base = unc + (size_t)b * HWSZ + (size_t)hy * 8 * WW + wx * 8;
            float s = 0.f;
            #pragma unroll
            for (int iy = 0; iy < 8; iy++)
                #pragma unroll
                for (int ix = 0; ix < 8; ix++) s += base[iy * WW + ix];
            unsigned int sb = __float_as_uint(s * (1.f / 64.f));
            key[i] = (((unsigned long long)sb) << 12) | (unsigned)(NWIN - 1 - i);
        }
        __syncthreads();
        for (int k = 2; k <= NWIN; k <<= 1)
            for (int j = k >> 1; j > 0; j >>= 1) {
                for (int i = tid; i < NWIN; i += 1024) {
                    int ixj = i ^ j;
                    if (ixj > i) {
                        unsigned long long a = key[i], c = key[ixj];
                        bool desc = ((i & k) == 0);
                        if (desc ? (a < c) : (a > c)) { key[i] = c; key[ixj] = a; }
                    }
                }
                __syncthreads();
            }
        for (int m = tid; m < NWF; m += 1024) {
            int idx = (NWIN - 1) - (int)(key[m] & 0xFFFULL);
            d_sel[b * NWF + m] = idx;
            atomicOr(&d_selmask[b * 128 + (idx >> 5)], 1u << (idx & 31));
        }
        return;
    }
    if (bid < BB + 6) {                  // ---- weight conversion ----
        int m = bid - BB;
        const float* src = (m == 0) ? qgw : (m == 1) ? l0w :
                           (m < 5) ? qkvw + (size_t)(m - 2) * 16384 : pw;
        for (int i = tid; i < 16384; i += 1024)
            d_whi[m][i] = __float2bfloat16_rn(__ldg(&src[i]));
        return;
    }
    // ---- pool only (no copy) ----
    int pid = bid - BB - 6;              // BB*CC*64
    int b = pid >> 13, c = (pid >> 6) & 127, p = pid & 63;
    int p0 = p >> 3, p1 = p & 7;
    size_t base_off = ((size_t)(b * CC + c) * HH + (size_t)p0 * 64) * WW + p1 * 64;
    const float* base = fm + base_off;
    // 4096 floats = 1024 float4: exactly one per thread
    int r = tid >> 4, col4 = (tid & 15) * 4;
    float4 v = *(const float4*)(base + (size_t)r * WW + col4);
    float s = (v.x + v.y) + (v.z + v.w);
    #pragma unroll
    for (int off = 16; off > 0; off >>= 1) s += __shfl_xor_sync(0xffffffffu, s, off);
    float* red = (float*)sm;
    if ((tid & 31) == 0) red[tid >> 5] = s;
    __syncthreads();
    if (tid == 0) {
        float tot = 0.f;
        #pragma unroll
        for (int q = 0; q < 32; q++) tot += red[q];
        d_g[(b * 64 + p) * CC + c] = tot * (1.f / 4096.f);
    }
}

// ============ global k/v projection (64 blocks) ============
__global__ void kv2_kernel(const float* __restrict__ kvw) {
    __shared__ float g[16 * 128];
    __shared__ float wt[32 * 129];
    int bid = blockIdx.x;                // b(1) which(1) cg(2) pg(2)
    int b = bid >> 5, which = (bid >> 4) & 1, cg = (bid >> 2) & 3, pg = bid & 3;
    int tid = threadIdx.x;               // 256
    for (int i = tid; i < 16 * 128; i += 256) g[i] = d_g[b * 64 * 128 + pg * 16 * 128 + i];
    const float* wb = kvw + ((size_t)(which * 128 + cg * 32)) * 128;
    for (int i = tid; i < 32 * 128; i += 256) wt[(i >> 7) * 129 + (i & 127)] = wb[i];
    __syncthreads();
    int cl = tid & 31, c = cg * 32 + cl;
    int pi = tid >> 5;                   // 0..7
    float s0 = 0.f, s1 = 0.f;
    for (int k = 0; k < 128; k++) {
        float wv = wt[cl * 129 + k];
        s0 = fmaf(g[(pi * 2) * 128 + k], wv, s0);
        s1 = fmaf(g[(pi * 2 + 1) * 128 + k], wv, s1);
    }
    int p = pg * 16 + pi * 2;
    __nv_bfloat16 h0 = __float2bfloat16_rn(s0), h1 = __float2bfloat16_rn(s1);
    if (which) { d_vgtb[b][c * 64 + p] = h0; d_vgtb[b][c * 64 + p + 1] = h1; }
    else       { d_kgb [b][p * 128 + c] = h0; d_kgb [b][(p + 1) * 128 + c] = h1; }
}

// weight copies
__device__ __forceinline__ void copy_w512(const __nv_bfloat16* __restrict__ src,
                                          __nv_bfloat16* dst, int tid) {
    int r = tid >> 2, q = tid & 3;
    const uint4* s = (const uint4*)(src + r * 128 + q * 32);
    uint4* d = (uint4*)(dst + r * SA + q * 32);
    d[0] = __ldg(&s[0]); d[1] = __ldg(&s[1]); d[2] = __ldg(&s[2]); d[3] = __ldg(&s[3]);
}
__device__ __forceinline__ void copy_w256(const __nv_bfloat16* __restrict__ src,
                                          __nv_bfloat16* dst, int t2) {
    int r = t2 >> 1, hf = t2 & 1;
    const uint4* s = (const uint4*)(src + r * 128 + hf * 64);
    uint4* d = (uint4*)(dst + r * SA + hf * 64);
    #pragma unroll
    for (int i = 0; i < 8; i++) d[i] = __ldg(&s[i]);
}

// ================= window kernel (+fused selective copy) =================
__global__ __launch_bounds__(512) void window_kernel(
    const float* __restrict__ fm,
    const float* __restrict__ l0b, const float* __restrict__ pb,
    float* __restrict__ out)
{
    extern __shared__ __align__(16) unsigned char smc[];
    __nv_bfloat16* WFH = (__nv_bfloat16*)(smc + O_A);
    __nv_bfloat16* WFL = (__nv_bfloat16*)(smc + O_B);
    __nv_bfloat16* WTH = (__nv_bfloat16*)(smc + O_C);
    __nv_bfloat16* WTL = (__nv_bfloat16*)(smc + O_D);
    __nv_bfloat16* EB  = (__nv_bfloat16*)(smc + O_E);
    __nv_bfloat16* KG  = (__nv_bfloat16*)(smc + O_F);
    __nv_bfloat16* VGT = (__nv_bfloat16*)(smc + O_VGT);
    __nv_bfloat16* PB  = (__nv_bfloat16*)(smc + O_P);
    float* DUMP  = (float*)(smc + O_E);
    float* bias1 = (float*)(smc);
    float* bias2 = (float*)(smc + 512);

    const int tid  = threadIdx.x;
    const int w    = tid >> 5, lane = tid & 31;
    const int g    = lane >> 2, t = lane & 3;
    const int rb2  = w & 3,  cq = w >> 2;
    const int r32  = rb2 * 32, c32 = cq * 32;
    const int wl2  = rb2 >> 1;
    const int sr0  = (w & 7) * 16;
    const int swl  = (w & 7) >> 2;

    const int b  = blockIdx.x / NPAIR;
    const int pr = blockIdx.x % NPAIR;

    // ---- P0: gather + biases + kv images + qg->WTH ----
    {
        int rr = tid >> 2, q4 = tid & 3;
        int wsel = d_sel[b * NWF + pr * 2 + (rr >> 6)];
        int hy = wsel >> 6, wx = wsel & 63, tk = rr & 63;
        const float* fb = fm + (size_t)b * CC * HWSZ + (size_t)(hy * 8 + (tk >> 3)) * WW + wx * 8 + (tk & 7);
        #pragma unroll 4
        for (int i = 0; i < 32; i += 2) {
            int c = q4 * 32 + i;
            float x0 = __ldg(fb + (size_t)c * HWSZ);
            float x1 = __ldg(fb + (size_t)(c + 1) * HWSZ);
            uint32_t h, l; split2(x0, x1, h, l);
            *(uint32_t*)&WFH[rr * SA + c] = h;
            *(uint32_t*)&WFL[rr * SA + c] = l;
        }
        if (tid < 128) { bias1[tid] = l0b[tid]; bias2[tid] = pb[tid]; }
        const uint32_t* sk = (const uint32_t*)d_kgb[b];
        const uint32_t* sv = (const uint32_t*)d_vgtb[b];
        for (int i = tid; i < 4096; i += 512) {
            int p = i >> 6, cp = i & 63;
            *(uint32_t*)&KG[p * SA + cp * 2] = sk[i];
            int c2 = i >> 5, pp = i & 31;
            *(uint32_t*)&VGT[c2 * SP + pp * 2] = sv[i];
        }
        copy_w512(d_whi[0], WTH, tid);
    }
    __syncthreads();

#define MGET(ROW, C, OUT2) { \
    float2 _h = up2(*(uint32_t*)&WFH[(ROW) * SA + (C)]); \
    float2 _l = up2(*(uint32_t*)&WFL[(ROW) * SA + (C)]); \
    OUT2 = make_float2(_h.x + _l.x, _h.y + _l.y); }
#define MPUT(ROW, C, X0, X1) { uint32_t _hh, _ll; split2(X0, X1, _hh, _ll); \
    *(uint32_t*)&WFH[(ROW) * SA + (C)] = _hh; *(uint32_t*)&WFL[(ROW) * SA + (C)] = _ll; }

#define STORE32(DST, S) { _Pragma("unroll") for (int mi = 0; mi < 2; mi++) \
    _Pragma("unroll") for (int nt = 0; nt < 4; nt++) { \
        float* a_ = acc[(mi * 2 + (nt >> 1)) * 2 + (nt & 1)]; \
        int r_ = r32 + mi * 16 + g, c_ = c32 + nt * 8 + 2 * t; \
        *(uint32_t*)&(DST)[r_ * (S) + c_]       = pkf(a_[0], a_[1]); \
        *(uint32_t*)&(DST)[(r_ + 8) * (S) + c_] = pkf(a_[2], a_[3]); } }

#define SOFTMAX64(SC, R0) { \
    float mxa = -1e30f, mxb = -1e30f; \
    _Pragma("unroll") for (int nt = 0; nt < 8; nt++) { \
        (SC)[nt][0] *= SCALEF; (SC)[nt][1] *= SCALEF; (SC)[nt][2] *= SCALEF; (SC)[nt][3] *= SCALEF; \
        mxa = fmaxf(mxa, fmaxf((SC)[nt][0], (SC)[nt][1])); \
        mxb = fmaxf(mxb, fmaxf((SC)[nt][2], (SC)[nt][3])); } \
    mxa = fmaxf(mxa, __shfl_xor_sync(0xffffffffu, mxa, 1)); \
    mxa = fmaxf(mxa, __shfl_xor_sync(0xffffffffu, mxa, 2)); \
    mxb = fmaxf(mxb, __shfl_xor_sync(0xffffffffu, mxb, 1)); \
    mxb = fmaxf(mxb, __shfl_xor_sync(0xffffffffu, mxb, 2)); \
    float ea = 0.f, eb = 0.f; \
    _Pragma("unroll") for (int nt = 0; nt < 8; nt++) { \
        (SC)[nt][0] = __expf((SC)[nt][0] - mxa); (SC)[nt][1] = __expf((SC)[nt][1] - mxa); \
        (SC)[nt][2] = __expf((SC)[nt][2] - mxb); (SC)[nt][3] = __expf((SC)[nt][3] - mxb); \
        ea += (SC)[nt][0] + (SC)[nt][1]; eb += (SC)[nt][2] + (SC)[nt][3]; } \
    ea += __shfl_xor_sync(0xffffffffu, ea, 1); ea += __shfl_xor_sync(0xffffffffu, ea, 2); \
    eb += __shfl_xor_sync(0xffffffffu, eb, 1); eb += __shfl_xor_sync(0xffffffffu, eb, 2); \
    float ia = 1.f / ea, ib = 1.f / eb; \
    _Pragma("unroll") for (int nt = 0; nt < 8; nt++) { int c = 8 * nt + 2 * t; \
        *(uint32_t*)&PB[((R0) + g) * SP + c]     = pkf((SC)[nt][0] * ia, (SC)[nt][1] * ia); \
        *(uint32_t*)&PB[((R0) + 8 + g) * SP + c] = pkf((SC)[nt][2] * ib, (SC)[nt][3] * ib); } }

    // ---- P1: q = wf @ Wq_g^T -> EB ----
    {
        float acc[8][4]; ZACC(acc, 8);
        gpassG<2, 2, 8>(acc, WFH, SA, r32, WTH, SA, c32, lane);
        STORE32(EB, SA);
    }
    __syncthreads();

    // ---- P2: cross scores+softmax (w<8) | l0->WTH, Wq2->WTL (w>=8) ----
    if (w < 8) {
        float sc[8][4]; ZACC(sc, 8);
        gpassG<1, 4, 8>(sc, EB, SA, sr0, KG, SA, 0, lane);
        SOFTMAX64(sc, sr0);
    } else {
        copy_w256(d_whi[1], WTH, tid - 256);
        copy_w256(d_whi[2], WTL, tid - 256);
    }
    __syncthreads();

    // ---- P3: AV = P @ vgT^T ; wf += AV ----
    {
        float acc[8][4]; ZACC(acc, 8);
        gpassG<2, 2, 4>(acc, PB, SP, r32, VGT, SP, c32, lane);
        #pragma unroll
        for (int mi = 0; mi < 2; mi++)
            #pragma unroll
            for (int nt = 0; nt < 4; nt++) {
                float* a_ = acc[(mi * 2 + (nt >> 1)) * 2 + (nt & 1)];
                int r_ = r32 + mi * 16 + g, c_ = c32 + nt * 8 + 2 * t;
                float2 m0; MGET(r_, c_, m0);
                MPUT(r_, c_, m0.x + a_[0], m0.y + a_[1]);
                float2 m1; MGET(r_ + 8, c_, m1);
                MPUT(r_ + 8, c_, m1.x + a_[2], m1.y + a_[3]);
            }
    }
    __syncthreads();

    // ---- P4: MLP1 + (tail) Wk2->WTH ----
    {
        float acc[8][4]; ZACC(acc, 8);
        gpassG<2, 2, 8>(acc, WFH, SA, r32, WTH, SA, c32, lane);
        #pragma unroll
        for (int mi = 0; mi < 2; mi++)
            #pragma unroll
            for (int nt = 0; nt < 4; nt++) {
                float* a_ = acc[(mi * 2 + (nt >> 1)) * 2 + (nt & 1)];
                int r_ = r32 + mi * 16 + g, c_ = c32 + nt * 8 + 2 * t;
                float2 m0; MGET(r_, c_, m0);
                a_[0] = m0.x + geluf(a_[0] + bias1[c_]);
                a_[1] = m0.y + geluf(a_[1] + bias1[c_ + 1]);
                float2 m1; MGET(r_ + 8, c_, m1);
                a_[2] = m1.x + geluf(a_[2] + bias1[c_]);
                a_[3] = m1.y + geluf(a_[3] + bias1[c_ + 1]);
            }
        __syncthreads();
        #pragma unroll
        for (int mi = 0; mi < 2; mi++)
            #pragma unroll
            for (int nt = 0; nt < 4; nt++) {
                float* a_ = acc[(mi * 2 + (nt >> 1)) * 2 + (nt & 1)];
                int r_ = r32 + mi * 16 + g, c_ = c32 + nt * 8 + 2 * t;
                MPUT(r_, c_, a_[0], a_[1]);
                MPUT(r_ + 8, c_, a_[2], a_[3]);
            }
        copy_w512(d_whi[3], WTH, tid);
    }
    __syncthreads();

    // ---- P5: q2 (w<8) -> EB | k2 (w>=8) -> KG ----
    {
        float acc[16][4]; ZACC(acc, 16);
        int rq = (w & 3) * 32;
        int ch = ((w >> 2) & 1) * 64;
        if (w < 8) {
            gpassG<2, 4, 8>(acc, WFH, SA, rq, WTL, SA, ch, lane);
            #pragma unroll
            for (int mi = 0; mi < 2; mi++)
                #pragma unroll
                for (int nt = 0; nt < 8; nt++) {
                    float* a_ = acc[(mi * 4 + (nt >> 1)) * 2 + (nt & 1)];
                    int r_ = rq + mi * 16 + g, c_ = ch + nt * 8 + 2 * t;
                    *(uint32_t*)&EB[r_ * SA + c_]       = pkf(a_[0], a_[1]);
                    *(uint32_t*)&EB[(r_ + 8) * SA + c_] = pkf(a_[2], a_[3]);
                }
        } else {
            gpassG<2, 4, 8>(acc, WFH, SA, rq, WTH, SA, ch, lane);
            #pragma unroll
            for (int mi = 0; mi < 2; mi++)
                #pragma unroll
                for (int nt = 0; nt < 8; nt++) {
                    float* a_ = acc[(mi * 4 + (nt >> 1)) * 2 + (nt & 1)];
                    int r_ = rq + mi * 16 + g, c_ = ch + nt * 8 + 2 * t;
                    *(uint32_t*)&KG[r_ * SA + c_]       = pkf(a_[0], a_[1]);
                    *(uint32_t*)&KG[(r_ + 8) * SA + c_] = pkf(a_[2], a_[3]);
                }
        }
    }
    __syncthreads();

    // ---- P6: self scores+softmax (w<8) | Wv2->WTL (w>=8) ----
    if (w < 8) {
        float sc[8][4]; ZACC(sc, 8);
        gpassG<1, 4, 8>(sc, EB, SA, sr0, KG, SA, swl * 64, lane);
        SOFTMAX64(sc, sr0);
    } else {
        copy_w256(d_whi[4], WTL, tid - 256);
    }
    __syncthreads();

    // ---- P7: v2T = Wv2 @ wf^T -> EB ----
    {
        float acc[8][4]; ZACC(acc, 8);
        gpassG<2, 2, 8>(acc, WTL, SA, r32, WFH, SA, c32, lane);
        STORE32(EB, SA);
    }
    __syncthreads();

    // ---- P8: AV2 = P2 @ v2 (all 16 warps) ----
    float av2[8][4];
    ZACC(av2, 8);
    gpassG<2, 2, 4>(av2, PB, SP, r32, EB + wl2 * 64, SA, c32, lane);
    __syncthreads();

    // ---- P9: dump AV2 -> DUMP ----
    #pragma unroll
    for (int mi = 0; mi < 2; mi++)
        #pragma unroll
        for (int nt = 0; nt < 4; nt++) {
            float* a_ = av2[(mi * 2 + (nt >> 1)) * 2 + (nt & 1)];
            int r_ = r32 + mi * 16 + g, c_ = c32 + nt * 8 + 2 * t;
            *(float2*)&DUMP[r_ * SD + c_]       = make_float2(a_[0], a_[1]);
            *(float2*)&DUMP[(r_ + 8) * SD + c_] = make_float2(a_[2], a_[3]);
        }
    __syncthreads();

    // ---- P10: quirk (w<8) | pw->WTH (w>=8) ----
    if (w < 8) {
        #pragma unroll
        for (int half = 0; half < 2; half++) {
            int rr_ = sr0 + half * 8 + g;
            int rA = rr_ & 63;
            #pragma unroll
            for (int nt = 0; nt < 16; nt++) {
                int c = nt * 8 + 2 * t;
                float2 m; MGET(rr_, c, m);
                int j0 = c, j1 = c + 1;
                m.x += DUMP[(swl * 64 + (j0 & 63)) * SD + (j0 >> 6) + 2 * rA];
                m.y += DUMP[(swl * 64 + (j1 & 63)) * SD + (j1 >> 6) + 2 * rA];
                MPUT(rr_, c, m.x, m.y);
            }
        }
    } else {
        copy_w256(d_whi[5], WTH, tid - 256);
    }
    __syncthreads();

    // ---- P11: MLP2 -> DUMP ----
    {
        float acc[8][4]; ZACC(acc, 8);
        gpassG<2, 2, 8>(acc, WFH, SA, r32, WTH, SA, c32, lane);
        #pragma unroll
        for (int mi = 0; mi < 2; mi++)
            #pragma unroll
            for (int nt = 0; nt < 4; nt++) {
                float* a_ = acc[(mi * 2 + (nt >> 1)) * 2 + (nt & 1)];
                int r_ = r32 + mi * 16 + g, c_ = c32 + nt * 8 + 2 * t;
                float2 m0; MGET(r_, c_, m0);
                float2 m1; MGET(r_ + 8, c_, m1);
                *(float2*)&DUMP[r_ * SD + c_] = make_float2(
                    m0.x + geluf(a_[0] + bias2[c_]), m0.y + geluf(a_[1] + bias2[c_ + 1]));
                *(float2*)&DUMP[(r_ + 8) * SD + c_] = make_float2(
                    m1.x + geluf(a_[2] + bias2[c_]), m1.y + geluf(a_[3] + bias2[c_ + 1]));
            }
    }
    __syncthreads();

    // ---- P12: scatter ----
    {
        int rr = tid >> 2, q4 = tid & 3;
        int wsel = d_sel[b * NWF + pr * 2 + (rr >> 6)];
        int hy = wsel >> 6, wx = wsel & 63, tk = rr & 63;
        float* ob = out + (size_t)b * CC * HWSZ + (size_t)(hy * 8 + (tk >> 3)) * WW + wx * 8 + (tk & 7);
        #pragma unroll 8
        for (int i = 0; i < 32; i++) {
            int c = q4 * 32 + i;
            ob[(size_t)c * HWSZ] = DUMP[rr * SD + c];
        }
    }

    // ---- P13: fused pass-through copy of unselected windows (own batch slice) ----
    {
        const size_t bbase = (size_t)b * CC * HWSZ;
        const unsigned* msk = &d_selmask[b * 128];
        const int total4 = (int)((CC * HWSZ) >> 2);     // 8,388,608
        for (int i4 = pr * 512 + tid; i4 < total4; i4 += NPAIR * 512) {
            int f = i4 << 2;
            int y = (f >> 9) & 511, x = f & 511;
            int wdw = ((y >> 3) << 6) + (x >> 3);
            if (!((__ldg(&msk[wdw >> 5]) >> (wdw & 31)) & 1)) {
                *(float4*)(out + bbase + f) = *(const float4*)(fm + bbase + f);
            }
        }
    }
#undef STORE32
#undef MGET
#undef MPUT
#undef SOFTMAX64
}

// =====================================================================
extern "C" void kernel_launch(void* const* d_in, const int* in_sizes, int n_in,
                              void* d_out, int out_size) {
    const float* fm   = (const float*)d_in[0];
    const float* unc  = (const float*)d_in[1];
    const float* qgw  = (const float*)d_in[2];
    const float* kvw  = (const float*)d_in[3];
    const float* l0w  = (const float*)d_in[4];
    const float* l0b  = (const float*)d_in[5];
    const float* qkvw = (const float*)d_in[6];
    const float* pw   = (const float*)d_in[7];
    const float* pb   = (const float*)d_in[8];
    float* out = (float*)d_out;

    cudaFuncSetAttribute(window_kernel, cudaFuncAttributeMaxDynamicSharedMemorySize, SMEM_SZ);

    prep_kernel<<<BB + 6 + BB * CC * 64, 1024>>>(unc, qgw, l0w, qkvw, pw, fm);
    kv2_kernel<<<64, 256>>>(kvw);
    window_kernel<<<BB * NPAIR, 512, SMEM_SZ>>>(fm, l0b, pb, out);
}

// round 14
// speedup vs baseline: 1.2853x; 1.2853x over previous
#include <cuda_runtime.h>
#include <cuda_bf16.h>
#include <math.h>
#include <stdint.h>

#define BB   2
#define CC   128
#define HH   512
#define WW   512
#define NWIN 4096
#define NWF  1228
#define NPAIR (NWF/2)
#define HWSZ ((size_t)HH*(size_t)WW)
#define SCALEF 0.08838834764831845f

// strides (elements)
#define SA 136
#define SP 72
#define SD 132

// smem byte offsets (window kernel)
#define O_A   1024
#define O_B   35840
#define O_C   70656
#define O_D   105472
#define O_E   140288
#define O_F   175104
#define O_VGT (O_F+17408)
#define O_P   210944
#define SMEM_SZ 229376

// -------- device scratch --------
__device__ int   d_sel[BB * NWF];
__device__ float d_part[BB * CC * 64 * 8];      // partial pools [b][c][wy][p1]
__device__ __nv_bfloat16 d_kgb[BB][64 * 128];
__device__ __nv_bfloat16 d_vgtb[BB][128 * 64];
// weight images (bf16): 0=qg 1=l0 2=q2 3=k2 4=v2 5=pw
__device__ __nv_bfloat16 d_whi[6][128 * 128];

// ---------------- helpers ----------------
__device__ __forceinline__ uint32_t pkf(float a, float b){
    __nv_bfloat162 t = __floats2bfloat162_rn(a, b);
    return *reinterpret_cast<uint32_t*>(&t);
}
__device__ __forceinline__ float2 up2(uint32_t u){
    __nv_bfloat162 b = *reinterpret_cast<__nv_bfloat162*>(&u);
    return make_float2(__bfloat162float(b.x), __bfloat162float(b.y));
}
__device__ __forceinline__ void split2(float x0, float x1, uint32_t& h, uint32_t& l){
    __nv_bfloat16 b0 = __float2bfloat16_rn(x0), b1 = __float2bfloat16_rn(x1);
    __nv_bfloat162 hb; hb.x = b0; hb.y = b1;
    h = *reinterpret_cast<uint32_t*>(&hb);
    l = pkf(x0 - __bfloat162float(b0), x1 - __bfloat162float(b1));
}
__device__ __forceinline__ float geluf(float x){
    return 0.5f * x * (1.f + erff(x * 0.70710678118654752f));
}
__device__ __forceinline__ void mma16816(float* d, const uint32_t* a, uint32_t b0, uint32_t b1){
    asm("mma.sync.aligned.m16n8k16.row.col.f32.bf16.bf16.f32 "
        "{%0,%1,%2,%3},{%4,%5,%6,%7},{%8,%9},{%0,%1,%2,%3};"
        : "+f"(d[0]), "+f"(d[1]), "+f"(d[2]), "+f"(d[3])
        : "r"(a[0]), "r"(a[1]), "r"(a[2]), "r"(a[3]), "r"(b0), "r"(b1));
}
__device__ __forceinline__ void ldsm4(uint32_t* r, uint32_t addr){
    asm volatile("ldmatrix.sync.aligned.m8n8.x4.shared.b16 {%0,%1,%2,%3}, [%4];"
        : "=r"(r[0]), "=r"(r[1]), "=r"(r[2]), "=r"(r[3]) : "r"(addr));
}

template<int MI, int NB, int KS>
__device__ __forceinline__ void gpassG(float (*acc)[4],
    const __nv_bfloat16* A, int sA, int arow0,
    const __nv_bfloat16* B, int sB, int bcol0, int lane)
{
    uint32_t aa[MI], bb[NB];
    uint32_t abase = (uint32_t)__cvta_generic_to_shared(
        A + (arow0 + (lane & 7) + (((lane >> 3) & 1) << 3)) * sA + ((lane >> 4) << 3));
    #pragma unroll
    for (int mi = 0; mi < MI; mi++) aa[mi] = abase + mi * 16 * sA * 2;
    uint32_t bbase = (uint32_t)__cvta_generic_to_shared(
        B + (bcol0 + (lane & 7) + ((lane >> 4) << 3)) * sB + (((lane >> 3) & 1) << 3));
    #pragma unroll
    for (int nb = 0; nb < NB; nb++) bb[nb] = bbase + nb * 16 * sB * 2;
    #pragma unroll
    for (int ks = 0; ks < KS; ks++) {
        uint32_t ar[MI][4];
        #pragma unroll
        for (int mi = 0; mi < MI; mi++) ldsm4(ar[mi], aa[mi] + ks * 32);
        #pragma unroll
        for (int nb = 0; nb < NB; nb++) {
            uint32_t rbv[4]; ldsm4(rbv, bb[nb] + ks * 32);
            #pragma unroll
            for (int mi = 0; mi < MI; mi++) {
                mma16816(acc[(mi * NB + nb) * 2],     ar[mi], rbv[0], rbv[1]);
                mma16816(acc[(mi * NB + nb) * 2 + 1], ar[mi], rbv[2], rbv[3]);
            }
        }
    }
}

#define ZACC(A, N) { _Pragma("unroll") for (int _i = 0; _i < (N); _i++) { (A)[_i][0]=0.f;(A)[_i][1]=0.f;(A)[_i][2]=0.f;(A)[_i][3]=0.f; } }

// ============ prep: sort+select | weight conv | streaming copy + partial pool ============
__global__ void prep_kernel(const float* __restrict__ unc,
                            const float* __restrict__ qgw,
                            const float* __restrict__ l0w,
                            const float* __restrict__ qkvw,
                            const float* __restrict__ pw,
                            const float* __restrict__ fm,
                            float* __restrict__ out) {
    __shared__ __align__(16) unsigned char sm[32768];
    int tid = threadIdx.x;               // 1024
    int bid = blockIdx.x;
    if (bid < BB) {                      // ---- sort/select ----
        unsigned long long* key = (unsigned long long*)sm;
        int b = bid;
        for (int i = tid; i < NWIN; i += 1024) {
            int hy = i >> 6, wx = i & 63;
            const float* base = unc + (size_t)b * HWSZ + (size_t)hy * 8 * WW + wx * 8;
            float s = 0.f;
            #pragma unroll
            for (int iy = 0; iy < 8; iy++)
                #pragma unroll
                for (int ix = 0; ix < 8; ix++) s += base[iy * WW + ix];
            unsigned int sb = __float_as_uint(s * (1.f / 64.f));
            key[i] = (((unsigned long long)sb) << 12) | (unsigned)(NWIN - 1 - i);
        }
        __syncthreads();
        for (int k = 2; k <= NWIN; k <<= 1)
            for (int j = k >> 1; j > 0; j >>= 1) {
                for (int i = tid; i < NWIN; i += 1024) {
                    int ixj = i ^ j;
                    if (ixj > i) {
                        unsigned long long a = key[i], c = key[ixj];
                        bool desc = ((i & k) == 0);
                        if (desc ? (a < c) : (a > c)) { key[i] = c; key[ixj] = a; }
                    }
                }
                __syncthreads();
            }
        for (int m = tid; m < NWF; m += 1024)
            d_sel[b * NWF + m] = (NWIN - 1) - (int)(key[m] & 0xFFFULL);
        return;
    }
    if (bid < BB + 6) {                  // ---- weight conversion ----
        int m = bid - BB;
        const float* src = (m == 0) ? qgw : (m == 1) ? l0w :
                           (m < 5) ? qkvw + (size_t)(m - 2) * 16384 : pw;
        for (int i = tid; i < 16384; i += 1024)
            d_whi[m][i] = __float2bfloat16_rn(__ldg(&src[i]));
        return;
    }
    // ---- streaming full copy + partial pool ----
    // block = (b, c, wy): 8 consecutive image rows = 16KB contiguous
    int pid = bid - BB - 6;              // BB*CC*64
    int wy = pid & 63;
    int c  = (pid >> 6) & 127;
    int b  = pid >> 13;
    size_t base_off = ((size_t)(b * CC + c) * HH + (size_t)wy * 8) * WW;
    const float4* src = (const float4*)(fm + base_off);
    float4* dst = (float4*)(out + base_off);
    // 1024 float4 per block, exactly 1 per thread
    float4 v = __ldg(&src[tid]);
    dst[tid] = v;
    float s = (v.x + v.y) + (v.z + v.w);
    // half-warp (16 lanes share same p1 = (tid&127)>>4) reduce
    s += __shfl_xor_sync(0xffffffffu, s, 1);
    s += __shfl_xor_sync(0xffffffffu, s, 2);
    s += __shfl_xor_sync(0xffffffffu, s, 4);
    s += __shfl_xor_sync(0xffffffffu, s, 8);
    float* part = (float*)sm;            // 64 slots
    int warp = tid >> 5, lane = tid & 31;
    if ((lane & 15) == 0) part[warp * 2 + (lane >> 4)] = s;
    __syncthreads();
    if (tid < 8) {
        // p1 = tid; contributors: warps w with (w&3)==tid>>1, half=tid&1
        float tot = 0.f;
        #pragma unroll
        for (int k = 0; k < 8; k++)
            tot += part[((tid >> 1) + 4 * k) * 2 + (tid & 1)];
        d_part[(((b * CC + c) * 64) + wy) * 8 + tid] = tot;
    }
}

// ============ global k/v projection (64 blocks; reduces partials) ============
__global__ void kv2_kernel(const float* __restrict__ kvw) {
    __shared__ float g[16 * 128];
    __shared__ float wt[32 * 129];
    int bid = blockIdx.x;                // b(1) which(1) cg(2) pg(2)
    int b = bid >> 5, which = (bid >> 4) & 1, cg = (bid >> 2) & 3, pg = bid & 3;
    int tid = threadIdx.x;               // 256
    // build g slice [16 p][128 c] from partials
    for (int i = tid; i < 16 * 128; i += 256) {
        int pl = i >> 7, c = i & 127;
        int p = pg * 16 + pl;
        int p0 = p >> 3, p1 = p & 7;
        const float* pp = &d_part[(((b * CC + c) * 64) + p0 * 8) * 8 + p1];
        float s = 0.f;
        #pragma unroll
        for (int j = 0; j < 8; j++) s += pp[j * 8];
        g[i] = s * (1.f / 4096.f);
    }
    const float* wb = kvw + ((size_t)(which * 128 + cg * 32)) * 128;
    for (int i = tid; i < 32 * 128; i += 256) wt[(i >> 7) * 129 + (i & 127)] = wb[i];
    __syncthreads();
    int cl = tid & 31, c = cg * 32 + cl;
    int pi = tid >> 5;                   // 0..7
    float s0 = 0.f, s1 = 0.f;
    for (int k = 0; k < 128; k++) {
        float wv = wt[cl * 129 + k];
        s0 = fmaf(g[(pi * 2) * 128 + k], wv, s0);
        s1 = fmaf(g[(pi * 2 + 1) * 128 + k], wv, s1);
    }
    int p = pg * 16 + pi * 2;
    __nv_bfloat16 h0 = __float2bfloat16_rn(s0), h1 = __float2bfloat16_rn(s1);
    if (which) { d_vgtb[b][c * 64 + p] = h0; d_vgtb[b][c * 64 + p + 1] = h1; }
    else       { d_kgb [b][p * 128 + c] = h0; d_kgb [b][(p + 1) * 128 + c] = h1; }
}

// weight copies
__device__ __forceinline__ void copy_w512(const __nv_bfloat16* __restrict__ src,
                                          __nv_bfloat16* dst, int tid) {
    int r = tid >> 2, q = tid & 3;
    const uint4* s = (const uint4*)(src + r * 128 + q * 32);
    uint4* d = (uint4*)(dst + r * SA + q * 32);
    d[0] = __ldg(&s[0]); d[1] = __ldg(&s[1]); d[2] = __ldg(&s[2]); d[3] = __ldg(&s[3]);
}
__device__ __forceinline__ void copy_w256(const __nv_bfloat16* __restrict__ src,
                                          __nv_bfloat16* dst, int t2) {
    int r = t2 >> 1, hf = t2 & 1;
    const uint4* s = (const uint4*)(src + r * 128 + hf * 64);
    uint4* d = (uint4*)(dst + r * SA + hf * 64);
    #pragma unroll
    for (int i = 0; i < 8; i++) d[i] = __ldg(&s[i]);
}

// ================= window kernel =================
__global__ __launch_bounds__(512) void window_kernel(
    const float* __restrict__ fm,
    const float* __restrict__ l0b, const float* __restrict__ pb,
    float* __restrict__ out)
{
    extern __shared__ __align__(16) unsigned char smc[];
    __nv_bfloat16* WFH = (__nv_bfloat16*)(smc + O_A);
    __nv_bfloat16* WFL = (__nv_bfloat16*)(smc + O_B);
    __nv_bfloat16* WTH = (__nv_bfloat16*)(smc + O_C);
    __nv_bfloat16* WTL = (__nv_bfloat16*)(smc + O_D);
    __nv_bfloat16* EB  = (__nv_bfloat16*)(smc + O_E);
    __nv_bfloat16* KG  = (__nv_bfloat16*)(smc + O_F);
    __nv_bfloat16* VGT = (__nv_bfloat16*)(smc + O_VGT);
    __nv_bfloat16* PB  = (__nv_bfloat16*)(smc + O_P);
    float* DUMP  = (float*)(smc + O_E);
    float* bias1 = (float*)(smc);
    float* bias2 = (float*)(smc + 512);

    const int tid  = threadIdx.x;
    const int w    = tid >> 5, lane = tid & 31;
    const int g    = lane >> 2, t = lane & 3;
    const int rb2  = w & 3,  cq = w >> 2;
    const int r32  = rb2 * 32, c32 = cq * 32;
    const int wl2  = rb2 >> 1;
    const int sr0  = (w & 7) * 16;
    const int swl  = (w & 7) >> 2;

    const int b  = blockIdx.x / NPAIR;
    const int pr = blockIdx.x % NPAIR;

    // ---- P0: gather + biases + kv images + qg->WTH ----
    {
        int rr = tid >> 2, q4 = tid & 3;
        int wsel = d_sel[b * NWF + pr * 2 + (rr >> 6)];
        int hy = wsel >> 6, wx = wsel & 63, tk = rr & 63;
        const float* fb = fm + (size_t)b * CC * HWSZ + (size_t)(hy * 8 + (tk >> 3)) * WW + wx * 8 + (tk & 7);
        #pragma unroll 4
        for (int i = 0; i < 32; i += 2) {
            int c = q4 * 32 + i;
            float x0 = __ldg(fb + (size_t)c * HWSZ);
            float x1 = __ldg(fb + (size_t)(c + 1) * HWSZ);
            uint32_t h, l; split2(x0, x1, h, l);
            *(uint32_t*)&WFH[rr * SA + c] = h;
            *(uint32_t*)&WFL[rr * SA + c] = l;
        }
        if (tid < 128) { bias1[tid] = l0b[tid]; bias2[tid] = pb[tid]; }
        const uint32_t* sk = (const uint32_t*)d_kgb[b];
        const uint32_t* sv = (const uint32_t*)d_vgtb[b];
        for (int i = tid; i < 4096; i += 512) {
            int p = i >> 6, cp = i & 63;
            *(uint32_t*)&KG[p * SA + cp * 2] = sk[i];
            int c2 = i >> 5, pp = i & 31;
            *(uint32_t*)&VGT[c2 * SP + pp * 2] = sv[i];
        }
        copy_w512(d_whi[0], WTH, tid);
    }
    __syncthreads();

#define MGET(ROW, C, OUT2) { \
    float2 _h = up2(*(uint32_t*)&WFH[(ROW) * SA + (C)]); \
    float2 _l = up2(*(uint32_t*)&WFL[(ROW) * SA + (C)]); \
    OUT2 = make_float2(_h.x + _l.x, _h.y + _l.y); }
#define MPUT(ROW, C, X0, X1) { uint32_t _hh, _ll; split2(X0, X1, _hh, _ll); \
    *(uint32_t*)&WFH[(ROW) * SA + (C)] = _hh; *(uint32_t*)&WFL[(ROW) * SA + (C)] = _ll; }

#define STORE32(DST, S) { _Pragma("unroll") for (int mi = 0; mi < 2; mi++) \
    _Pragma("unroll") for (int nt = 0; nt < 4; nt++) { \
        float* a_ = acc[(mi * 2 + (nt >> 1)) * 2 + (nt & 1)]; \
        int r_ = r32 + mi * 16 + g, c_ = c32 + nt * 8 + 2 * t; \
        *(uint32_t*)&(DST)[r_ * (S) + c_]       = pkf(a_[0], a_[1]); \
        *(uint32_t*)&(DST)[(r_ + 8) * (S) + c_] = pkf(a_[2], a_[3]); } }

#define SOFTMAX64(SC, R0) { \
    float mxa = -1e30f, mxb = -1e30f; \
    _Pragma("unroll") for (int nt = 0; nt < 8; nt++) { \
        (SC)[nt][0] *= SCALEF; (SC)[nt][1] *= SCALEF; (SC)[nt][2] *= SCALEF; (SC)[nt][3] *= SCALEF; \
        mxa = fmaxf(mxa, fmaxf((SC)[nt][0], (SC)[nt][1])); \
        mxb = fmaxf(mxb, fmaxf((SC)[nt][2], (SC)[nt][3])); } \
    mxa = fmaxf(mxa, __shfl_xor_sync(0xffffffffu, mxa, 1)); \
    mxa = fmaxf(mxa, __shfl_xor_sync(0xffffffffu, mxa, 2)); \
    mxb = fmaxf(mxb, __shfl_xor_sync(0xffffffffu, mxb, 1)); \
    mxb = fmaxf(mxb, __shfl_xor_sync(0xffffffffu, mxb, 2)); \
    float ea = 0.f, eb = 0.f; \
    _Pragma("unroll") for (int nt = 0; nt < 8; nt++) { \
        (SC)[nt][0] = __expf((SC)[nt][0] - mxa); (SC)[nt][1] = __expf((SC)[nt][1] - mxa); \
        (SC)[nt][2] = __expf((SC)[nt][2] - mxb); (SC)[nt][3] = __expf((SC)[nt][3] - mxb); \
        ea += (SC)[nt][0] + (SC)[nt][1]; eb += (SC)[nt][2] + (SC)[nt][3]; } \
    ea += __shfl_xor_sync(0xffffffffu, ea, 1); ea += __shfl_xor_sync(0xffffffffu, ea, 2); \
    eb += __shfl_xor_sync(0xffffffffu, eb, 1); eb += __shfl_xor_sync(0xffffffffu, eb, 2); \
    float ia = 1.f / ea, ib = 1.f / eb; \
    _Pragma("unroll") for (int nt = 0; nt < 8; nt++) { int c = 8 * nt + 2 * t; \
        *(uint32_t*)&PB[((R0) + g) * SP + c]     = pkf((SC)[nt][0] * ia, (SC)[nt][1] * ia); \
        *(uint32_t*)&PB[((R0) + 8 + g) * SP + c] = pkf((SC)[nt][2] * ib, (SC)[nt][3] * ib); } }

    // ---- P1: q = wf @ Wq_g^T -> EB ----
    {
        float acc[8][4]; ZACC(acc, 8);
        gpassG<2, 2, 8>(acc, WFH, SA, r32, WTH, SA, c32, lane);
        STORE32(EB, SA);
    }
    __syncthreads();

    // ---- P2: cross scores+softmax (w<8) | l0->WTH, Wq2->WTL (w>=8) ----
    if (w < 8) {
        float sc[8][4]; ZACC(sc, 8);
        gpassG<1, 4, 8>(sc, EB, SA, sr0, KG, SA, 0, lane);
        SOFTMAX64(sc, sr0);
    } else {
        copy_w256(d_whi[1], WTH, tid - 256);
        copy_w256(d_whi[2], WTL, tid - 256);
    }
    __syncthreads();

    // ---- P3: AV = P @ vgT^T ; wf += AV ----
    {
        float acc[8][4]; ZACC(acc, 8);
        gpassG<2, 2, 4>(acc, PB, SP, r32, VGT, SP, c32, lane);
        #pragma unroll
        for (int mi = 0; mi < 2; mi++)
            #pragma unroll
            for (int nt = 0; nt < 4; nt++) {
                float* a_ = acc[(mi * 2 + (nt >> 1)) * 2 + (nt & 1)];
                int r_ = r32 + mi * 16 + g, c_ = c32 + nt * 8 + 2 * t;
                float2 m0; MGET(r_, c_, m0);
                MPUT(r_, c_, m0.x + a_[0], m0.y + a_[1]);
                float2 m1; MGET(r_ + 8, c_, m1);
                MPUT(r_ + 8, c_, m1.x + a_[2], m1.y + a_[3]);
            }
    }
    __syncthreads();

    // ---- P4: MLP1 + (tail) Wk2->WTH ----
    {
        float acc[8][4]; ZACC(acc, 8);
        gpassG<2, 2, 8>(acc, WFH, SA, r32, WTH, SA, c32, lane);
        #pragma unroll
        for (int mi = 0; mi < 2; mi++)
            #pragma unroll
            for (int nt = 0; nt < 4; nt++) {
                float* a_ = acc[(mi * 2 + (nt >> 1)) * 2 + (nt & 1)];
                int r_ = r32 + mi * 16 + g, c_ = c32 + nt * 8 + 2 * t;
                float2 m0; MGET(r_, c_, m0);
                a_[0] = m0.x + geluf(a_[0] + bias1[c_]);
                a_[1] = m0.y + geluf(a_[1] + bias1[c_ + 1]);
                float2 m1; MGET(r_ + 8, c_, m1);
                a_[2] = m1.x + geluf(a_[2] + bias1[c_]);
                a_[3] = m1.y + geluf(a_[3] + bias1[c_ + 1]);
            }
        __syncthreads();
        #pragma unroll
        for (int mi = 0; mi < 2; mi++)
            #pragma unroll
            for (int nt = 0; nt < 4; nt++) {
                float* a_ = acc[(mi * 2 + (nt >> 1)) * 2 + (nt & 1)];
                int r_ = r32 + mi * 16 + g, c_ = c32 + nt * 8 + 2 * t;
                MPUT(r_, c_, a_[0], a_[1]);
                MPUT(r_ + 8, c_, a_[2], a_[3]);
            }
        copy_w512(d_whi[3], WTH, tid);
    }
    __syncthreads();

    // ---- P5: q2 (w<8) -> EB | k2 (w>=8) -> KG ----
    {
        float acc[16][4]; ZACC(acc, 16);
        int rq = (w & 3) * 32;
        int ch = ((w >> 2) & 1) * 64;
        if (w < 8) {
            gpassG<2, 4, 8>(acc, WFH, SA, rq, WTL, SA, ch, lane);
            #pragma unroll
            for (int mi = 0; mi < 2; mi++)
                #pragma unroll
                for (int nt = 0; nt < 8; nt++) {
                    float* a_ = acc[(mi * 4 + (nt >> 1)) * 2 + (nt & 1)];
                    int r_ = rq + mi * 16 + g, c_ = ch + nt * 8 + 2 * t;
                    *(uint32_t*)&EB[r_ * SA + c_]       = pkf(a_[0], a_[1]);
                    *(uint32_t*)&EB[(r_ + 8) * SA + c_] = pkf(a_[2], a_[3]);
                }
        } else {
            gpassG<2, 4, 8>(acc, WFH, SA, rq, WTH, SA, ch, lane);
            #pragma unroll
            for (int mi = 0; mi < 2; mi++)
                #pragma unroll
                for (int nt = 0; nt < 8; nt++) {
                    float* a_ = acc[(mi * 4 + (nt >> 1)) * 2 + (nt & 1)];
                    int r_ = rq + mi * 16 + g, c_ = ch + nt * 8 + 2 * t;
                    *(uint32_t*)&KG[r_ * SA + c_]       = pkf(a_[0], a_[1]);
                    *(uint32_t*)&KG[(r_ + 8) * SA + c_] = pkf(a_[2], a_[3]);
                }
        }
    }
    __syncthreads();

    // ---- P6: self scores+softmax (w<8) | Wv2->WTL (w>=8) ----
    if (w < 8) {
        float sc[8][4]; ZACC(sc, 8);
        gpassG<1, 4, 8>(sc, EB, SA, sr0, KG, SA, swl * 64, lane);
        SOFTMAX64(sc, sr0);
    } else {
        copy_w256(d_whi[4], WTL, tid - 256);
    }
    __syncthreads();

    // ---- P7: v2T = Wv2 @ wf^T -> EB ----
    {
        float acc[8][4]; ZACC(acc, 8);
        gpassG<2, 2, 8>(acc, WTL, SA, r32, WFH, SA, c32, lane);
        STORE32(EB, SA);
    }
    __syncthreads();

    // ---- P8: AV2 = P2 @ v2 (all 16 warps) ----
    float av2[8][4];
    ZACC(av2, 8);
    gpassG<2, 2, 4>(av2, PB, SP, r32, EB + wl2 * 64, SA, c32, lane);
    __syncthreads();

    // ---- P9: dump AV2 -> DUMP ----
    #pragma unroll
    for (int mi = 0; mi < 2; mi++)
        #pragma unroll
        for (int nt = 0; nt < 4; nt++) {
            float* a_ = av2[(mi * 2 + (nt >> 1)) * 2 + (nt & 1)];
            int r_ = r32 + mi * 16 + g, c_ = c32 + nt * 8 + 2 * t;
            *(float2*)&DUMP[r_ * SD + c_]       = make_float2(a_[0], a_[1]);
            *(float2*)&DUMP[(r_ + 8) * SD + c_] = make_float2(a_[2], a_[3]);
        }
    __syncthreads();

    // ---- P10: quirk (w<8) | pw->WTH (w>=8) ----
    if (w < 8) {
        #pragma unroll
        for (int half = 0; half < 2; half++) {
            int rr_ = sr0 + half * 8 + g;
            int rA = rr_ & 63;
            #pragma unroll
            for (int nt = 0; nt < 16; nt++) {
                int c = nt * 8 + 2 * t;
                float2 m; MGET(rr_, c, m);
                int j0 = c, j1 = c + 1;
                m.x += DUMP[(swl * 64 + (j0 & 63)) * SD + (j0 >> 6) + 2 * rA];
                m.y += DUMP[(swl * 64 + (j1 & 63)) * SD + (j1 >> 6) + 2 * rA];
                MPUT(rr_, c, m.x, m.y);
            }
        }
    } else {
        copy_w256(d_whi[5], WTH, tid - 256);
    }
    __syncthreads();

    // ---- P11: MLP2 -> DUMP ----
    {
        float acc[8][4]; ZACC(acc, 8);
        gpassG<2, 2, 8>(acc, WFH, SA, r32, WTH, SA, c32, lane);
        #pragma unroll
        for (int mi = 0; mi < 2; mi++)
            #pragma unroll
            for (int nt = 0; nt < 4; nt++) {
                float* a_ = acc[(mi * 2 + (nt >> 1)) * 2 + (nt & 1)];
                int r_ = r32 + mi * 16 + g, c_ = c32 + nt * 8 + 2 * t;
                float2 m0; MGET(r_, c_, m0);
                float2 m1; MGET(r_ + 8, c_, m1);
                *(float2*)&DUMP[r_ * SD + c_] = make_float2(
                    m0.x + geluf(a_[0] + bias2[c_]), m0.y + geluf(a_[1] + bias2[c_ + 1]));
                *(float2*)&DUMP[(r_ + 8) * SD + c_] = make_float2(
                    m1.x + geluf(a_[2] + bias2[c_]), m1.y + geluf(a_[3] + bias2[c_ + 1]));
            }
    }
    __syncthreads();

    // ---- P12: scatter ----
    {
        int rr = tid >> 2, q4 = tid & 3;
        int wsel = d_sel[b * NWF + pr * 2 + (rr >> 6)];
        int hy = wsel >> 6, wx = wsel & 63, tk = rr & 63;
        float* ob = out + (size_t)b * CC * HWSZ + (size_t)(hy * 8 + (tk >> 3)) * WW + wx * 8 + (tk & 7);
        #pragma unroll 8
        for (int i = 0; i < 32; i++) {
            int c = q4 * 32 + i;
            ob[(size_t)c * HWSZ] = DUMP[rr * SD + c];
        }
    }
#undef STORE32
#undef MGET
#undef MPUT
#undef SOFTMAX64
}

// =====================================================================
extern "C" void kernel_launch(void* const* d_in, const int* in_sizes, int n_in,
                              void* d_out, int out_size) {
    const float* fm   = (const float*)d_in[0];
    const float* unc  = (const float*)d_in[1];
    const float* qgw  = (const float*)d_in[2];
    const float* kvw  = (const float*)d_in[3];
    const float* l0w  = (const float*)d_in[4];
    const float* l0b  = (const float*)d_in[5];
    const float* qkvw = (const float*)d_in[6];
    const float* pw   = (const float*)d_in[7];
    const float* pb   = (const float*)d_in[8];
    float* out = (float*)d_out;

    cudaFuncSetAttribute(window_kernel, cudaFuncAttributeMaxDynamicSharedMemorySize, SMEM_SZ);

    prep_kernel<<<BB + 6 + BB * CC * 64, 1024>>>(unc, qgw, l0w, qkvw, pw, fm, out);
    kv2_kernel<<<64, 256>>>(kvw);
    window_kernel<<<BB * NPAIR, 512, SMEM_SZ>>>(fm, l0b, pb, out);
}